// round 17
// baseline (speedup 1.0000x reference)
#include <cuda_runtime.h>
#include <cuda_bf16.h>
#include <mma.h>
#include <cstdint>

// Sparse 3x3x3 conv block, 2 layers, N=64, D=128 — wmma bf16 split-precision.
// tcgen05 unavailable (harness compiles compute_103 PTX, no 'a' features);
// use portable wmma (HMMA) bf16 16x16x16: out = xhi@Whi + xhi@Wlo + xlo@Whi
// in fp32 accum (~1e-5 rel err vs 1e-3 budget). Center tap dense (STG+bias),
// 26 neighbor taps gather+red.v4. Weights pre-split to bf16 hi/lo (stride 80).
// CRITICAL: device symbols (g_h, g_Wt,...) NEVER passed from host (GB300 ATS
// host-shadow trap, R8/R9: 7x regression). nullptr sentinels only.

#define DG   128
#define NCH  64
#define MAXM 131072
#define NOFF 27
#define CENTER 13
#define LDAB 80          // bf16 stride for A/B tiles (160B: 32B-aligned rows)
#define LDD  72          // f32 stride for D bounce

using namespace nvcuda;

__device__ __align__(16) int   g_lookup[DG * DG * DG];
__device__ __align__(16) int   g_cnt[NOFF];
__device__ __align__(16) int   g_pout[NOFF * MAXM];
__device__ __align__(16) int   g_pin [NOFF * MAXM];
__device__ __align__(16) float g_h   [MAXM * NCH];
// per (layer,k): [hi 64x80][lo 64x80] bf16, W as-is (j-major, no transpose)
__device__ __align__(16) __nv_bfloat16 g_Wt[2 * NOFF * 2 * 64 * LDAB];

// ---------------------------------------------------------------------------
__global__ void k_fill(int nquad) {
    int i = blockIdx.x * blockDim.x + threadIdx.x;
    if (i < nquad) ((int4*)g_lookup)[i] = make_int4(-1, -1, -1, -1);
    if (i < NOFF)  g_cnt[i] = 0;
}

__global__ void k_scatter(const int* __restrict__ coords, int M) {
    int i = blockIdx.x * blockDim.x + threadIdx.x;
    if (i >= M) return;
    int x = coords[3 * i + 0];
    int y = coords[3 * i + 1];
    int z = coords[3 * i + 2];
    g_lookup[(x * DG + y) * DG + z] = i;
}

// Pair lists for 26 non-center offsets: pipelined lookups, block-aggregated
// counts, one atomic per block per offset.
__global__ void __launch_bounds__(256) k_pairs(const int* __restrict__ coords, int M) {
    __shared__ int swpre[NOFF][8];
    __shared__ int sbase[NOFF];
    int tid  = threadIdx.x;
    int lane = tid & 31;
    int wid  = tid >> 5;
    int i    = blockIdx.x * 256 + tid;
    bool act = (i < M) && (i < MAXM);
    int cx = 0, cy = 0, cz = 0;
    if (act) {
        cx = coords[3 * i + 0];
        cy = coords[3 * i + 1];
        cz = coords[3 * i + 2];
    }
    int nidx[NOFF];
#pragma unroll
    for (int k = 0; k < NOFF; k++) {
        nidx[k] = -1;
        if (k == CENTER) continue;
        int dx = k / 9 - 1, dy = (k / 3) % 3 - 1, dz = k % 3 - 1;
        if (act) {
            int nx = cx + dx, ny = cy + dy, nz = cz + dz;
            if (nx >= 0 && nx < DG && ny >= 0 && ny < DG && nz >= 0 && nz < DG)
                nidx[k] = g_lookup[(nx * DG + ny) * DG + nz];
        }
    }
#pragma unroll
    for (int k = 0; k < NOFF; k++) {
        if (k == CENTER) continue;
        unsigned m = __ballot_sync(0xffffffffu, nidx[k] >= 0);
        if (lane == 0) swpre[k][wid] = __popc(m);
    }
    __syncthreads();
    if (tid < NOFF && tid != CENTER) {
        int s = 0;
#pragma unroll
        for (int w = 0; w < 8; w++) { int t = swpre[tid][w]; swpre[tid][w] = s; s += t; }
        sbase[tid] = s ? atomicAdd(&g_cnt[tid], s) : 0;
    }
    __syncthreads();
#pragma unroll
    for (int k = 0; k < NOFF; k++) {
        if (k == CENTER) continue;
        unsigned m = __ballot_sync(0xffffffffu, nidx[k] >= 0);
        if (nidx[k] >= 0) {
            int pos = k * MAXM + sbase[k] + swpre[k][wid] + __popc(m & ((1u << lane) - 1));
            g_pout[pos] = i;
            g_pin [pos] = nidx[k];
        }
    }
}

// Weight prep: split W[j][c] (as stored, j-major) into bf16 hi/lo, stride 80.
// One block per (layer, offset).
__global__ void k_wprep(const float* __restrict__ W1, const float* __restrict__ W2) {
    int b = blockIdx.x;
    int layer = b / NOFF, k = b % NOFF;
    const float* W = (layer ? W2 : W1) + k * 4096;
    __nv_bfloat16* dh = g_Wt + (size_t)(layer * NOFF + k) * (2 * 64 * LDAB);
    __nv_bfloat16* dl = dh + 64 * LDAB;
    for (int e = threadIdx.x; e < 4096; e += blockDim.x) {
        int j = e >> 6, c = e & 63;
        float v = W[e];
        __nv_bfloat16 h = __float2bfloat16(v);
        float hf = __bfloat162float(h);
        dh[j * LDAB + c] = h;
        dl[j * LDAB + c] = __float2bfloat16(v - hf);
    }
}

__global__ void k_relu4(float4* __restrict__ x, int nquad) {
    int i = blockIdx.x * blockDim.x + threadIdx.x;
    if (i < nquad) {
        float4 v = x[i];
        v.x = fmaxf(v.x, 0.f); v.y = fmaxf(v.y, 0.f);
        v.z = fmaxf(v.z, 0.f); v.w = fmaxf(v.w, 0.f);
        x[i] = v;
    }
}

// ---------------------------------------------------------------------------
__device__ __forceinline__ void red4(float* p, float a, float b, float c, float d) {
    asm volatile("red.global.add.v4.f32 [%0], {%1, %2, %3, %4};"
                 :: "l"(p), "f"(a), "f"(b), "f"(c), "f"(d) : "memory");
}
#define CVTBF2(res, a, b) \
    asm("cvt.rn.satfinite.bf16x2.f32 %0, %1, %2;" : "=r"(res) : "f"(b), "f"(a))

// ---------------------------------------------------------------------------
// Tensor conv. GATHER=false: dense center tap (STG+bias). GATHER=true:
// 26 neighbor offsets via in-block tile prefix, red.v4 scatter.
// Dyn smem (256-aligned base):
//   aHi 0..20480 | aLo 20480..40960 | bHi 40960..51200 | bLo 51200..61440
//   | spref 61440.. ; D bounce (128 x LDD f32 = 36864B) reuses aHi/aLo.
#define DYNSMEM 61952
template<bool GATHER, bool RELU>
__global__ void k_tconv(const float* xin, const float* __restrict__ bias,
                        float* outp, int layer, int M) {
    extern __shared__ char dyn[];
    char* sm = (char*)(((uintptr_t)dyn + 255) & ~(uintptr_t)255);
    __nv_bfloat16* aHi = (__nv_bfloat16*)sm;                 // [128][LDAB]
    __nv_bfloat16* aLo = (__nv_bfloat16*)(sm + 20480);
    __nv_bfloat16* bHi = (__nv_bfloat16*)(sm + 40960);       // [64][LDAB]
    __nv_bfloat16* bLo = (__nv_bfloat16*)(sm + 51200);
    int*   spref = (int*)(sm + 61440);
    float* Dsh   = (float*)sm;                                // [128][LDD]

    const float* x = xin  ? xin  : (const float*)g_h;
    float* out     = outp ? outp : g_h;
    int tx = threadIdx.x;
    int wr = (tx >> 5) * 32;      // warp's 32-row slice

    if (tx == 0 && GATHER) {
        int s = 0;
        for (int k = 0; k < NOFF; k++) {
            spref[k] = s;
            if (k != CENTER) s += (g_cnt[k] + 127) >> 7;
        }
        spref[NOFF] = s;
    }
    __syncthreads();

    int ntiles = GATHER ? spref[NOFF] : ((M + 127) >> 7);

    for (int ti = blockIdx.x; ti < ntiles; ti += gridDim.x) {
        int k, base, ctile;
        if (GATHER) {
            int kk = 0;
            while (ti >= spref[kk + 1]) kk++;
            k = kk;
            base = (ti - spref[kk]) * 128;
            int c = g_cnt[k] - base;
            ctile = c > 128 ? 128 : c;
        } else {
            k = CENTER;
            base = ti * 128;
            int c = M - base;
            ctile = c > 128 ? 128 : c;
        }
        __syncthreads();   // previous tile's D bounce fully consumed

        // Stage B: hi+lo contiguous, 20480 B = 1280 uint4 (10/thread)
        {
            const uint4* wsrc = (const uint4*)(g_Wt + (size_t)(layer * NOFF + k) * (2 * 64 * LDAB));
            uint4* wdst = (uint4*)bHi;
#pragma unroll
            for (int q = 0; q < 10; q++) wdst[tx + q * 128] = wsrc[tx + q * 128];
        }

        // Stage A row tx: fp32 -> bf16 hi/lo
        int gidx = -1;
        if (tx < ctile) gidx = GATHER ? g_pin[k * MAXM + base + tx] : (base + tx);
        uint32_t* ahr = (uint32_t*)(aHi + tx * LDAB);
        uint32_t* alr = (uint32_t*)(aLo + tx * LDAB);
        if (gidx >= 0) {
            const float4* r4 = (const float4*)(x + (size_t)gidx * NCH);
#pragma unroll
            for (int c = 0; c < 8; c++) {
                float4 va = r4[2 * c], vb = r4[2 * c + 1];
                if (RELU) {
                    va.x = fmaxf(va.x, 0.f); va.y = fmaxf(va.y, 0.f);
                    va.z = fmaxf(va.z, 0.f); va.w = fmaxf(va.w, 0.f);
                    vb.x = fmaxf(vb.x, 0.f); vb.y = fmaxf(vb.y, 0.f);
                    vb.z = fmaxf(vb.z, 0.f); vb.w = fmaxf(vb.w, 0.f);
                }
                uint32_t h0, h1, h2, h3;
                CVTBF2(h0, va.x, va.y); CVTBF2(h1, va.z, va.w);
                CVTBF2(h2, vb.x, vb.y); CVTBF2(h3, vb.z, vb.w);
                float e0 = va.x - __uint_as_float(h0 << 16);
                float e1 = va.y - __uint_as_float(h0 & 0xffff0000u);
                float e2 = va.z - __uint_as_float(h1 << 16);
                float e3 = va.w - __uint_as_float(h1 & 0xffff0000u);
                float e4 = vb.x - __uint_as_float(h2 << 16);
                float e5 = vb.y - __uint_as_float(h2 & 0xffff0000u);
                float e6 = vb.z - __uint_as_float(h3 << 16);
                float e7 = vb.w - __uint_as_float(h3 & 0xffff0000u);
                uint32_t l0, l1, l2, l3;
                CVTBF2(l0, e0, e1); CVTBF2(l1, e2, e3);
                CVTBF2(l2, e4, e5); CVTBF2(l3, e6, e7);
                ahr[4 * c + 0] = h0; ahr[4 * c + 1] = h1;
                ahr[4 * c + 2] = h2; ahr[4 * c + 3] = h3;
                alr[4 * c + 0] = l0; alr[4 * c + 1] = l1;
                alr[4 * c + 2] = l2; alr[4 * c + 3] = l3;
            }
        } else {
#pragma unroll
            for (int c = 0; c < 16; c++) { ahr[c * 2] = 0; ahr[c * 2 + 1] = 0;
                                           alr[c * 2] = 0; alr[c * 2 + 1] = 0; }
        }
        __syncthreads();

        // Compute: per warp 32 rows x 64 cols = 2x4 wmma tiles, 3 splits x K64
        wmma::fragment<wmma::accumulator, 16, 16, 16, float> acc[2][4];
#pragma unroll
        for (int rg = 0; rg < 2; rg++)
#pragma unroll
            for (int cg = 0; cg < 4; cg++) wmma::fill_fragment(acc[rg][cg], 0.0f);

#pragma unroll
        for (int split = 0; split < 3; split++) {
            const __nv_bfloat16* As = (split < 2) ? aHi : aLo;
            const __nv_bfloat16* Bs = (split == 1) ? bLo : bHi;
#pragma unroll
            for (int ks = 0; ks < 4; ks++) {
                wmma::fragment<wmma::matrix_a, 16, 16, 16, __nv_bfloat16, wmma::row_major> af0, af1;
                wmma::load_matrix_sync(af0, As + (wr + 0)  * LDAB + ks * 16, LDAB);
                wmma::load_matrix_sync(af1, As + (wr + 16) * LDAB + ks * 16, LDAB);
#pragma unroll
                for (int cg = 0; cg < 4; cg++) {
                    wmma::fragment<wmma::matrix_b, 16, 16, 16, __nv_bfloat16, wmma::row_major> bf;
                    wmma::load_matrix_sync(bf, Bs + (ks * 16) * LDAB + cg * 16, LDAB);
                    wmma::mma_sync(acc[0][cg], af0, bf, acc[0][cg]);
                    wmma::mma_sync(acc[1][cg], af1, bf, acc[1][cg]);
                }
            }
        }

        __syncthreads();   // all warps done reading A before D overwrites it
#pragma unroll
        for (int rg = 0; rg < 2; rg++)
#pragma unroll
            for (int cg = 0; cg < 4; cg++)
                wmma::store_matrix_sync(Dsh + (wr + rg * 16) * LDD + cg * 16,
                                        acc[rg][cg], LDD, wmma::mem_row_major);
        __syncthreads();

        // Epilogue: thread tx owns point tx (row of D)
        if (tx < ctile) {
            const float* dr = Dsh + tx * LDD;
            if (GATHER) {
                int row = g_pout[k * MAXM + base + tx];
                float* o = out + (size_t)row * NCH;
#pragma unroll
                for (int q = 0; q < 16; q++)
                    red4(o + q * 4, dr[4 * q], dr[4 * q + 1], dr[4 * q + 2], dr[4 * q + 3]);
            } else {
                float* o = out + (size_t)(base + tx) * NCH;
                const float4* b4 = (const float4*)bias;
#pragma unroll
                for (int q = 0; q < 16; q++) {
                    float4 bb = b4[q];
                    ((float4*)o)[q] = make_float4(dr[4 * q] + bb.x, dr[4 * q + 1] + bb.y,
                                                  dr[4 * q + 2] + bb.z, dr[4 * q + 3] + bb.w);
                }
            }
        }
    }
}

// ---------------------------------------------------------------------------
extern "C" void kernel_launch(void* const* d_in, const int* in_sizes, int n_in,
                              void* d_out, int out_size) {
    const float* feats  = (const float*)d_in[0];
    const float* W1     = (const float*)d_in[1];
    const float* b1     = (const float*)d_in[2];
    const float* W2     = (const float*)d_in[3];
    const float* b2     = (const float*)d_in[4];
    const int*   coords = (const int*)d_in[5];
    int M = in_sizes[0] / NCH;
    float* out = (float*)d_out;

    cudaFuncSetAttribute(k_tconv<false, false>, cudaFuncAttributeMaxDynamicSharedMemorySize, DYNSMEM);
    cudaFuncSetAttribute(k_tconv<false, true>,  cudaFuncAttributeMaxDynamicSharedMemorySize, DYNSMEM);
    cudaFuncSetAttribute(k_tconv<true, false>,  cudaFuncAttributeMaxDynamicSharedMemorySize, DYNSMEM);
    cudaFuncSetAttribute(k_tconv<true, true>,   cudaFuncAttributeMaxDynamicSharedMemorySize, DYNSMEM);

    int vq = (DG * DG * DG) / 4;
    k_fill<<<(vq + 255) / 256, 256>>>(vq);
    k_scatter<<<(M + 255) / 256, 256>>>(coords, M);
    k_pairs<<<(M + 255) / 256, 256>>>(coords, M);
    k_wprep<<<2 * NOFF, 128>>>(W1, W2);

    const int GRID = 444;   // 3 blocks/SM x 148 SMs (62KB smem/block)

    // Layer 1: g_h = b1 + conv(feats, W1)   (g_h via in-kernel symbol)
    k_tconv<false, false><<<GRID, 128, DYNSMEM>>>(feats, b1, nullptr, 0, M);
    k_tconv<true,  false><<<GRID, 128, DYNSMEM>>>(feats, b1, nullptr, 0, M);

    // Layer 2: out = b2 + conv(relu(g_h), W2)  (ReLU fused into staging)
    k_tconv<false, true><<<GRID, 128, DYNSMEM>>>(nullptr, b2, out, 1, M);
    k_tconv<true,  true><<<GRID, 128, DYNSMEM>>>(nullptr, b2, out, 1, M);

    int Mq = M * (NCH / 4);
    k_relu4<<<(Mq + 255) / 256, 256>>>((float4*)out, Mq);
}